// round 15
// baseline (speedup 1.0000x reference)
#include <cuda_runtime.h>
#include <cuda_fp16.h>
#include <cstdint>

#define N_NODES 100000
#define N_REL   4
#define N_EDGES 600000
#define D       128
#define KTOT    (N_REL * D)   // 512
#define RN      (N_REL * N_NODES)   // 400000
#define TOT_EDGES (N_REL * N_EDGES) // 2400000
#define SCAN_BLK 1024
#define SCAN_NBLK ((N_NODES + SCAN_BLK - 1) / SCAN_BLK)   // 98

// Scratch (device globals — no allocation allowed in kernel_launch)
__device__ __half g_Y [(size_t)N_NODES * KTOT];      // [N, 4, 128] fp16: rs_out*(X@W_r)
__device__ __half g_Xh[(size_t)N_NODES * D];         // X in fp16
__device__ __half g_Wt[(size_t)N_REL * D * D];       // W[r] transposed: [r][n][k] fp16
__device__ int    g_cnt_out[RN];                     // out-degree  [r][n]
__device__ int    g_cnt_in [RN];                     // in-degree   [r][n]
__device__ int    g_rowptr [N_NODES + 1];            // CSR row ptr over dst nodes
__device__ int    g_cursor [N_NODES];                // fill cursors
__device__ int    g_blocksum[SCAN_NBLK];             // per-block totals (phase 1)
__device__ int    g_blockoff[SCAN_NBLK];             // exclusive block offsets (phase 2)
__device__ int    g_csr    [TOT_EDGES];              // packed (4*src + rel) by dst

// ---------------------------------------------------------------------------
// Degree histogram: one thread per (relation, edge), two int atomics.
__global__ void degree_kernel(const int* __restrict__ edges) {
    int i = blockIdx.x * blockDim.x + threadIdx.x;
    if (i >= TOT_EDGES) return;
    int r = i / N_EDGES;
    int e = i - r * N_EDGES;
    int s = edges[(r * 2 + 0) * N_EDGES + e];
    int t = edges[(r * 2 + 1) * N_EDGES + e];
    atomicAdd(&g_cnt_out[r * N_NODES + s], 1);
    atomicAdd(&g_cnt_in [r * N_NODES + t], 1);
}

// ---------------------------------------------------------------------------
// 3-phase parallel exclusive scan over combined in-degree per dst node.
__global__ __launch_bounds__(SCAN_BLK) void scan_phase1_kernel() {
    __shared__ int s[SCAN_BLK];
    int tid = threadIdx.x;
    int i = blockIdx.x * SCAN_BLK + tid;
    int v = 0;
    if (i < N_NODES) {
        v = __ldg(&g_cnt_in[0 * N_NODES + i]) + __ldg(&g_cnt_in[1 * N_NODES + i])
          + __ldg(&g_cnt_in[2 * N_NODES + i]) + __ldg(&g_cnt_in[3 * N_NODES + i]);
    }
    s[tid] = v;
    __syncthreads();
#pragma unroll
    for (int off = 1; off < SCAN_BLK; off <<= 1) {
        int add = (tid >= off) ? s[tid - off] : 0;
        __syncthreads();
        s[tid] += add;
        __syncthreads();
    }
    if (i < N_NODES) g_rowptr[i] = s[tid] - v;
    if (tid == SCAN_BLK - 1) g_blocksum[blockIdx.x] = s[tid];
}

__global__ __launch_bounds__(128) void scan_phase2_kernel() {
    __shared__ int s[128];
    int tid = threadIdx.x;
    int v = (tid < SCAN_NBLK) ? g_blocksum[tid] : 0;
    s[tid] = v;
    __syncthreads();
#pragma unroll
    for (int off = 1; off < 128; off <<= 1) {
        int add = (tid >= off) ? s[tid - off] : 0;
        __syncthreads();
        s[tid] += add;
        __syncthreads();
    }
    if (tid < SCAN_NBLK) g_blockoff[tid] = s[tid] - v;
    if (tid == 0) g_rowptr[N_NODES] = TOT_EDGES;
}

__global__ __launch_bounds__(SCAN_BLK) void scan_phase3_kernel() {
    int i = blockIdx.x * SCAN_BLK + threadIdx.x;
    if (i >= N_NODES) return;
    int v = g_rowptr[i] + __ldg(&g_blockoff[blockIdx.x]);
    g_rowptr[i] = v;
    g_cursor[i] = v;
}

// ---------------------------------------------------------------------------
// CSR fill: per edge, grab a slot in its dst bucket, store packed (4*src+rel).
__global__ void csr_fill_kernel(const int* __restrict__ edges) {
    int i = blockIdx.x * blockDim.x + threadIdx.x;
    if (i >= TOT_EDGES) return;
    int r = i / N_EDGES;
    int e = i - r * N_EDGES;
    int s = edges[(r * 2 + 0) * N_EDGES + e];
    int t = edges[(r * 2 + 1) * N_EDGES + e];
    int slot = atomicAdd(&g_cursor[t], 1);
    g_csr[slot] = (s << 2) | r;
}

// ---------------------------------------------------------------------------
// One-time conversions.
__global__ void convert_x_kernel(const float* __restrict__ X) {
    int i = blockIdx.x * blockDim.x + threadIdx.x;
    size_t total8 = (size_t)N_NODES * D / 8;
    if ((size_t)i >= total8) return;
    const float4* src = (const float4*)X + (size_t)i * 2;
    float4 a = __ldg(src);
    float4 b = __ldg(src + 1);
    __half2 h0 = __floats2half2_rn(a.x, a.y);
    __half2 h1 = __floats2half2_rn(a.z, a.w);
    __half2 h2 = __floats2half2_rn(b.x, b.y);
    __half2 h3 = __floats2half2_rn(b.z, b.w);
    uint4 u;
    u.x = *(uint32_t*)&h0; u.y = *(uint32_t*)&h1;
    u.z = *(uint32_t*)&h2; u.w = *(uint32_t*)&h3;
    *((uint4*)g_Xh + i) = u;
}

// W[r][k][n] f32 -> g_Wt[r][n][k] f16 (transposed per relation).
__global__ void convert_w_kernel(const float* __restrict__ W) {
    int i = blockIdx.x * blockDim.x + threadIdx.x;
    if (i >= N_REL * D * D) return;
    int r = i >> 14;
    int rem = i & 16383;
    int k = rem >> 7;
    int n = rem & 127;
    g_Wt[((size_t)r * D + n) * D + k] = __float2half_rn(__ldg(&W[i]));
}

// ---------------------------------------------------------------------------
// FP16 tensor-core GEMM producing Y' = rs_out_r * (Xh @ W_r), stored fp16.
// C-block 128x128; grid.y = relation. K = 128, BK = 32, DOUBLE-BUFFERED
// cp.async staging (prefetch tile k+1 during MMA on tile k).
// 8 warps (2M x 4N), warp tile 64x32, m16n8k16 f16 mma, f32 acc, ldmatrix.
#define GBM 128
#define GBN 128
#define GBK 32
#define SSTRIDE 20     // words per row (BK=32 halves = 16 words + 4 pad)

__device__ __forceinline__ void mma_f16(float* d, const uint32_t* a,
                                        const uint32_t* b) {
    asm volatile(
        "mma.sync.aligned.m16n8k16.row.col.f32.f16.f16.f32 "
        "{%0,%1,%2,%3}, {%4,%5,%6,%7}, {%8,%9}, {%0,%1,%2,%3};"
        : "+f"(d[0]), "+f"(d[1]), "+f"(d[2]), "+f"(d[3])
        : "r"(a[0]), "r"(a[1]), "r"(a[2]), "r"(a[3]), "r"(b[0]), "r"(b[1]));
}

__device__ __forceinline__ void ldsm_x4(uint32_t* r, uint32_t addr) {
    asm volatile("ldmatrix.sync.aligned.m8n8.x4.shared.b16 {%0,%1,%2,%3}, [%4];"
                 : "=r"(r[0]), "=r"(r[1]), "=r"(r[2]), "=r"(r[3]) : "r"(addr));
}

__device__ __forceinline__ void ldsm_x2(uint32_t* r, uint32_t addr) {
    asm volatile("ldmatrix.sync.aligned.m8n8.x2.shared.b16 {%0,%1}, [%2];"
                 : "=r"(r[0]), "=r"(r[1]) : "r"(addr));
}

__device__ __forceinline__ void cp16(uint32_t smem_addr, const void* gptr) {
    asm volatile("cp.async.cg.shared.global [%0], [%1], 16;"
                 :: "r"(smem_addr), "l"(gptr) : "memory");
}

__global__ __launch_bounds__(256, 2)
void gemm_f16_kernel(const __half* __restrict__ Xh, const __half* __restrict__ Wt,
                     __half* __restrict__ Y) {
    // Two buffers: 2 x 128 x 20 words x 4 B = 10.24 KB each array -> 41 KB total.
    __shared__ __align__(16) uint32_t As[2][GBM][SSTRIDE];
    __shared__ __align__(16) uint32_t Bs[2][GBN][SSTRIDE];

    int tid  = threadIdx.x;
    int wid  = tid >> 5;
    int lane = tid & 31;
    int lg   = lane >> 2;
    int lt   = lane & 3;
    int warp_m = wid & 1;
    int warp_n = wid >> 1;
    int row0 = blockIdx.x * GBM;
    int rel  = blockIdx.y;
    const __half* Bt = Wt + (size_t)rel * (D * D);

    uint32_t sA = (uint32_t)__cvta_generic_to_shared(&As[0][0][0]);
    uint32_t sB = (uint32_t)__cvta_generic_to_shared(&Bs[0][0][0]);
    const uint32_t BUFB = (uint32_t)(GBM * SSTRIDE * 4);   // bytes per buffer

    // Staging coords: each thread copies 2 A-chunks + 2 B-chunks (16 B each).
    // A: row = tid>>1, chunks (tid&1)*2 + {0,1} of 4 per row (32 halves).
    int st_row = tid >> 1;
    int st_ch0 = (tid & 1) * 2;
    int st_grow = min(row0 + st_row, N_NODES - 1);

    // ldmatrix lane geometry.
    int a_row_l  = warp_m * 64 + (lane & 7) + ((lane >> 3) & 1) * 8;
    int a_word_l = (lane >> 4) * 4;
    int b_col_l  = warp_n * 32 + ((lane & 15) & 7);
    int b_word_l = (((lane & 15) >> 3)) * 4;

    float acc[4][4][4];
#pragma unroll
    for (int mi = 0; mi < 4; mi++)
#pragma unroll
        for (int ni = 0; ni < 4; ni++)
#pragma unroll
            for (int j = 0; j < 4; j++) acc[mi][ni][j] = 0.0f;

    // Prologue: stage k0 = 0 into buffer 0.
#pragma unroll
    for (int c = 0; c < 2; c++) {
        int ch = st_ch0 + c;
        cp16(sA + (uint32_t)((st_row * SSTRIDE + ch * 4) * 4),
             Xh + (size_t)st_grow * D + 0 + ch * 8);
        cp16(sB + (uint32_t)((st_row * SSTRIDE + ch * 4) * 4),
             Bt + (size_t)st_row * D + 0 + ch * 8);
    }
    asm volatile("cp.async.commit_group;" ::: "memory");

    int buf = 0;
#pragma unroll
    for (int it = 0; it < 4; it++) {
        asm volatile("cp.async.wait_group 0;" ::: "memory");
        __syncthreads();

        // Prefetch next k-tile into the other buffer (its previous MMA
        // finished two iterations ago, guarded by the post-MMA sync).
        if (it < 3) {
            int k0 = (it + 1) * GBK;
            uint32_t ob = (uint32_t)(buf ^ 1) * BUFB;
#pragma unroll
            for (int c = 0; c < 2; c++) {
                int ch = st_ch0 + c;
                cp16(sA + ob + (uint32_t)((st_row * SSTRIDE + ch * 4) * 4),
                     Xh + (size_t)st_grow * D + k0 + ch * 8);
                cp16(sB + ob + (uint32_t)((st_row * SSTRIDE + ch * 4) * 4),
                     Bt + (size_t)st_row * D + k0 + ch * 8);
            }
            asm volatile("cp.async.commit_group;" ::: "memory");
        }

        uint32_t ab = sA + (uint32_t)buf * BUFB;
        uint32_t bb = sB + (uint32_t)buf * BUFB;
#pragma unroll
        for (int ks = 0; ks < 2; ks++) {      // two k16 steps per BK=32
            int kc = ks * 8;
            uint32_t af[4][4];
            uint32_t bf[4][2];
#pragma unroll
            for (int mi = 0; mi < 4; mi++) {
                uint32_t addr = ab + (uint32_t)(((a_row_l + mi * 16) * SSTRIDE
                                                 + kc + a_word_l) * 4);
                ldsm_x4(af[mi], addr);
            }
#pragma unroll
            for (int ni = 0; ni < 4; ni++) {
                uint32_t addr = bb + (uint32_t)(((b_col_l + ni * 8) * SSTRIDE
                                                 + kc + b_word_l) * 4);
                ldsm_x2(bf[ni], addr);
            }
#pragma unroll
            for (int mi = 0; mi < 4; mi++)
#pragma unroll
                for (int ni = 0; ni < 4; ni++)
                    mma_f16(acc[mi][ni], af[mi], bf[ni]);
        }
        __syncthreads();
        buf ^= 1;
    }

    // Epilogue: scale by rsqrt(max(deg_out,1)) computed inline from counts.
    const int* cnt_out = g_cnt_out + (size_t)rel * N_NODES;
#pragma unroll
    for (int mi = 0; mi < 4; mi++) {
        int r = row0 + warp_m * 64 + mi * 16 + lg;
        float s0 = 0.0f, s1 = 0.0f;
        if (r < N_NODES)
            s0 = rsqrtf(fmaxf((float)__ldg(&cnt_out[r]), 1.0f));
        if (r + 8 < N_NODES)
            s1 = rsqrtf(fmaxf((float)__ldg(&cnt_out[r + 8]), 1.0f));
#pragma unroll
        for (int ni = 0; ni < 4; ni++) {
            int c = warp_n * 32 + ni * 8 + 2 * lt;
            if (r < N_NODES) {
                __half2 h = __floats2half2_rn(acc[mi][ni][0] * s0,
                                              acc[mi][ni][1] * s0);
                *(__half2*)(Y + (size_t)r * KTOT + rel * D + c) = h;
            }
            if (r + 8 < N_NODES) {
                __half2 h = __floats2half2_rn(acc[mi][ni][2] * s1,
                                              acc[mi][ni][3] * s1);
                *(__half2*)(Y + (size_t)(r + 8) * KTOT + rel * D + c) = h;
            }
        }
    }
}

// ---------------------------------------------------------------------------
// Gather: one warp per dst node, single merged loop, 8-edge unrolled for
// deep MLP. Packed csr p = 4*src+rel is the Y row index; per-edge coef
// rsqrt(deg_in[rel][t]) selected from 4 preloaded registers via p&3.
__device__ __forceinline__ float sel4(int r, float c0, float c1, float c2,
                                      float c3) {
    return (r == 0) ? c0 : (r == 1) ? c1 : (r == 2) ? c2 : c3;
}

__global__ __launch_bounds__(256)
void gather_kernel(const __half* __restrict__ Y, float* __restrict__ out) {
    int warp = (blockIdx.x * blockDim.x + threadIdx.x) >> 5;
    if (warp >= N_NODES) return;
    int lane = threadIdx.x & 31;
    int t = warp;

    int start = __ldg(&g_rowptr[t]);
    int end   = __ldg(&g_rowptr[t + 1]);
    float cs0 = rsqrtf(fmaxf((float)__ldg(&g_cnt_in[0 * N_NODES + t]), 1.0f));
    float cs1 = rsqrtf(fmaxf((float)__ldg(&g_cnt_in[1 * N_NODES + t]), 1.0f));
    float cs2 = rsqrtf(fmaxf((float)__ldg(&g_cnt_in[2 * N_NODES + t]), 1.0f));
    float cs3 = rsqrtf(fmaxf((float)__ldg(&g_cnt_in[3 * N_NODES + t]), 1.0f));

    float a0 = 0.f, a1 = 0.f, a2 = 0.f, a3 = 0.f;

    int j = start;
    for (; j + 8 <= end; j += 8) {
        int p[8];
        uint2 v[8];
#pragma unroll
        for (int k = 0; k < 8; k++) p[k] = __ldg(&g_csr[j + k]);
#pragma unroll
        for (int k = 0; k < 8; k++)
            v[k] = __ldg((const uint2*)(Y + (size_t)p[k] * D) + lane);
#pragma unroll
        for (int k = 0; k < 8; k++) {
            float c = sel4(p[k] & 3, cs0, cs1, cs2, cs3);
            float2 x0 = __half22float2(*(__half2*)&v[k].x);
            float2 x1 = __half22float2(*(__half2*)&v[k].y);
            a0 = fmaf(c, x0.x, a0); a1 = fmaf(c, x0.y, a1);
            a2 = fmaf(c, x1.x, a2); a3 = fmaf(c, x1.y, a3);
        }
    }
    for (; j + 4 <= end; j += 4) {
        int p[4];
        uint2 v[4];
#pragma unroll
        for (int k = 0; k < 4; k++) p[k] = __ldg(&g_csr[j + k]);
#pragma unroll
        for (int k = 0; k < 4; k++)
            v[k] = __ldg((const uint2*)(Y + (size_t)p[k] * D) + lane);
#pragma unroll
        for (int k = 0; k < 4; k++) {
            float c = sel4(p[k] & 3, cs0, cs1, cs2, cs3);
            float2 x0 = __half22float2(*(__half2*)&v[k].x);
            float2 x1 = __half22float2(*(__half2*)&v[k].y);
            a0 = fmaf(c, x0.x, a0); a1 = fmaf(c, x0.y, a1);
            a2 = fmaf(c, x1.x, a2); a3 = fmaf(c, x1.y, a3);
        }
    }
    for (; j < end; j++) {
        int p0 = __ldg(&g_csr[j]);
        uint2 v0 = __ldg((const uint2*)(Y + (size_t)p0 * D) + lane);
        float c = sel4(p0 & 3, cs0, cs1, cs2, cs3);
        float2 x0 = __half22float2(*(__half2*)&v0.x);
        float2 x1 = __half22float2(*(__half2*)&v0.y);
        a0 = fmaf(c, x0.x, a0); a1 = fmaf(c, x0.y, a1);
        a2 = fmaf(c, x1.x, a2); a3 = fmaf(c, x1.y, a3);
    }

    float4 o = make_float4(a0, a1, a2, a3);
    *(float4*)(out + (size_t)t * D + lane * 4) = o;
}

// ---------------------------------------------------------------------------
extern "C" void kernel_launch(void* const* d_in, const int* in_sizes, int n_in,
                              void* d_out, int out_size) {
    const int*   edges = (const int*)d_in[0];    // [4, 2, 600000] int32
    const float* X     = (const float*)d_in[1];  // [100000, 128] f32
    const float* W     = (const float*)d_in[2];  // [4, 128, 128] f32
    float*       out   = (float*)d_out;          // [100000, 128] f32

    void *yp, *xhp, *wtp, *cop, *cip;
    cudaGetSymbolAddress(&yp,  g_Y);
    cudaGetSymbolAddress(&xhp, g_Xh);
    cudaGetSymbolAddress(&wtp, g_Wt);
    cudaGetSymbolAddress(&cop, g_cnt_out);
    cudaGetSymbolAddress(&cip, g_cnt_in);

    cudaMemsetAsync(cop, 0, sizeof(int) * RN, 0);
    cudaMemsetAsync(cip, 0, sizeof(int) * RN, 0);

    {
        degree_kernel<<<(TOT_EDGES + 255) / 256, 256>>>(edges);
    }
    {
        size_t total8 = (size_t)N_NODES * D / 8;
        convert_x_kernel<<<(int)((total8 + 255) / 256), 256>>>(X);
    }
    {
        int total = N_REL * D * D;
        convert_w_kernel<<<(total + 255) / 256, 256>>>(W);
    }
    scan_phase1_kernel<<<SCAN_NBLK, SCAN_BLK>>>();
    scan_phase2_kernel<<<1, 128>>>();
    scan_phase3_kernel<<<SCAN_NBLK, SCAN_BLK>>>();
    {
        csr_fill_kernel<<<(TOT_EDGES + 255) / 256, 256>>>(edges);
    }
    {
        dim3 grid((N_NODES + GBM - 1) / GBM, N_REL);   // (782, 4)
        gemm_f16_kernel<<<grid, 256>>>((const __half*)xhp, (const __half*)wtp,
                                       (__half*)yp);
    }
    {
        long long threads = (long long)N_NODES * 32;
        int blocks = (int)((threads + 255) / 256);
        gather_kernel<<<blocks, 256>>>((const __half*)yp, out);
    }
}

// round 16
// speedup vs baseline: 1.0172x; 1.0172x over previous
#include <cuda_runtime.h>
#include <cuda_fp16.h>
#include <cstdint>

#define N_NODES 100000
#define N_REL   4
#define N_EDGES 600000
#define D       128
#define KTOT    (N_REL * D)   // 512
#define RN      (N_REL * N_NODES)   // 400000
#define TOT_EDGES (N_REL * N_EDGES) // 2400000
#define SCAN_BLK 1024
#define SCAN_NBLK ((N_NODES + SCAN_BLK - 1) / SCAN_BLK)   // 98

// Scratch (device globals — no allocation allowed in kernel_launch)
__device__ __half g_Y [(size_t)N_NODES * KTOT];      // [N, 4, 128] fp16: rs_out*(X@W_r)
__device__ __half g_Xh[(size_t)N_NODES * D];         // X in fp16
__device__ __half g_Wt[(size_t)N_REL * D * D];       // W[r] transposed: [r][n][k] fp16
__device__ int    g_cnt_out[RN];                     // out-degree  [r][n]
__device__ int    g_cnt_in [RN];                     // in-degree   [r][n]
__device__ int    g_rowptr [N_NODES + 1];            // CSR row ptr over dst nodes
__device__ int    g_cursor [N_NODES];                // fill cursors
__device__ int    g_blocksum[SCAN_NBLK];             // per-block totals (phase 1)
__device__ int    g_blockoff[SCAN_NBLK];             // exclusive block offsets (phase 2)
__device__ int    g_csr    [TOT_EDGES];              // packed (4*src + rel) by dst

// ---------------------------------------------------------------------------
// Degree histogram: one thread per (relation, edge), two int atomics.
__global__ void degree_kernel(const int* __restrict__ edges) {
    int i = blockIdx.x * blockDim.x + threadIdx.x;
    if (i >= TOT_EDGES) return;
    int r = i / N_EDGES;
    int e = i - r * N_EDGES;
    int s = edges[(r * 2 + 0) * N_EDGES + e];
    int t = edges[(r * 2 + 1) * N_EDGES + e];
    atomicAdd(&g_cnt_out[r * N_NODES + s], 1);
    atomicAdd(&g_cnt_in [r * N_NODES + t], 1);
}

// ---------------------------------------------------------------------------
// 3-phase parallel exclusive scan over combined in-degree per dst node.
__global__ __launch_bounds__(SCAN_BLK) void scan_phase1_kernel() {
    __shared__ int s[SCAN_BLK];
    int tid = threadIdx.x;
    int i = blockIdx.x * SCAN_BLK + tid;
    int v = 0;
    if (i < N_NODES) {
        v = __ldg(&g_cnt_in[0 * N_NODES + i]) + __ldg(&g_cnt_in[1 * N_NODES + i])
          + __ldg(&g_cnt_in[2 * N_NODES + i]) + __ldg(&g_cnt_in[3 * N_NODES + i]);
    }
    s[tid] = v;
    __syncthreads();
#pragma unroll
    for (int off = 1; off < SCAN_BLK; off <<= 1) {
        int add = (tid >= off) ? s[tid - off] : 0;
        __syncthreads();
        s[tid] += add;
        __syncthreads();
    }
    if (i < N_NODES) g_rowptr[i] = s[tid] - v;
    if (tid == SCAN_BLK - 1) g_blocksum[blockIdx.x] = s[tid];
}

__global__ __launch_bounds__(128) void scan_phase2_kernel() {
    __shared__ int s[128];
    int tid = threadIdx.x;
    int v = (tid < SCAN_NBLK) ? g_blocksum[tid] : 0;
    s[tid] = v;
    __syncthreads();
#pragma unroll
    for (int off = 1; off < 128; off <<= 1) {
        int add = (tid >= off) ? s[tid - off] : 0;
        __syncthreads();
        s[tid] += add;
        __syncthreads();
    }
    if (tid < SCAN_NBLK) g_blockoff[tid] = s[tid] - v;
    if (tid == 0) g_rowptr[N_NODES] = TOT_EDGES;
}

__global__ __launch_bounds__(SCAN_BLK) void scan_phase3_kernel() {
    int i = blockIdx.x * SCAN_BLK + threadIdx.x;
    if (i >= N_NODES) return;
    int v = g_rowptr[i] + __ldg(&g_blockoff[blockIdx.x]);
    g_rowptr[i] = v;
    g_cursor[i] = v;
}

// ---------------------------------------------------------------------------
// CSR fill: per edge, grab a slot in its dst bucket, store packed (4*src+rel).
__global__ void csr_fill_kernel(const int* __restrict__ edges) {
    int i = blockIdx.x * blockDim.x + threadIdx.x;
    if (i >= TOT_EDGES) return;
    int r = i / N_EDGES;
    int e = i - r * N_EDGES;
    int s = edges[(r * 2 + 0) * N_EDGES + e];
    int t = edges[(r * 2 + 1) * N_EDGES + e];
    int slot = atomicAdd(&g_cursor[t], 1);
    g_csr[slot] = (s << 2) | r;
}

// ---------------------------------------------------------------------------
// One-time conversions.
__global__ void convert_x_kernel(const float* __restrict__ X) {
    int i = blockIdx.x * blockDim.x + threadIdx.x;
    size_t total8 = (size_t)N_NODES * D / 8;
    if ((size_t)i >= total8) return;
    const float4* src = (const float4*)X + (size_t)i * 2;
    float4 a = __ldg(src);
    float4 b = __ldg(src + 1);
    __half2 h0 = __floats2half2_rn(a.x, a.y);
    __half2 h1 = __floats2half2_rn(a.z, a.w);
    __half2 h2 = __floats2half2_rn(b.x, b.y);
    __half2 h3 = __floats2half2_rn(b.z, b.w);
    uint4 u;
    u.x = *(uint32_t*)&h0; u.y = *(uint32_t*)&h1;
    u.z = *(uint32_t*)&h2; u.w = *(uint32_t*)&h3;
    *((uint4*)g_Xh + i) = u;
}

// W[r][k][n] f32 -> g_Wt[r][n][k] f16 (transposed per relation).
__global__ void convert_w_kernel(const float* __restrict__ W) {
    int i = blockIdx.x * blockDim.x + threadIdx.x;
    if (i >= N_REL * D * D) return;
    int r = i >> 14;
    int rem = i & 16383;
    int k = rem >> 7;
    int n = rem & 127;
    g_Wt[((size_t)r * D + n) * D + k] = __float2half_rn(__ldg(&W[i]));
}

// ---------------------------------------------------------------------------
// FP16 tensor-core GEMM producing Y' = rs_out_r * (Xh @ W_r), stored fp16.
// C-block: 128x128; grid.y = relation. K = 128, BK = 64 (2 k-iterations).
// 8 warps (2M x 4N), warp tile 64x32, m16n8k16 f16 mma, f32 acc.
// Smem: half2 words, 32 words per BK=64 row, stride 36 -> conflict-free frags.
// (Exact R11 champion configuration.)
#define GBM 128
#define GBN 128
#define GBK 64
#define SSTRIDE 36

__device__ __forceinline__ void mma_f16(float* d, const uint32_t* a,
                                        const uint32_t* b) {
    asm volatile(
        "mma.sync.aligned.m16n8k16.row.col.f32.f16.f16.f32 "
        "{%0,%1,%2,%3}, {%4,%5,%6,%7}, {%8,%9}, {%0,%1,%2,%3};"
        : "+f"(d[0]), "+f"(d[1]), "+f"(d[2]), "+f"(d[3])
        : "r"(a[0]), "r"(a[1]), "r"(a[2]), "r"(a[3]), "r"(b[0]), "r"(b[1]));
}

__global__ __launch_bounds__(256, 2)
void gemm_f16_kernel(const __half* __restrict__ Xh, const __half* __restrict__ Wt,
                     __half* __restrict__ Y) {
    __shared__ __align__(16) uint32_t As[GBM][SSTRIDE];
    __shared__ __align__(16) uint32_t Bs[GBN][SSTRIDE];

    int tid  = threadIdx.x;
    int wid  = tid >> 5;
    int lane = tid & 31;
    int lg   = lane >> 2;
    int lt   = lane & 3;
    int warp_m = wid & 1;
    int warp_n = wid >> 1;
    int row0 = blockIdx.x * GBM;
    int rel  = blockIdx.y;
    const __half* Bt = Wt + (size_t)rel * (D * D);

    float acc[4][4][4];
#pragma unroll
    for (int mi = 0; mi < 4; mi++)
#pragma unroll
        for (int ni = 0; ni < 4; ni++)
#pragma unroll
            for (int j = 0; j < 4; j++) acc[mi][ni][j] = 0.0f;

    for (int k0 = 0; k0 < D; k0 += GBK) {
        // Stage A: 128 rows x 64 halves = 1024 uint4 chunks, 4 per thread.
#pragma unroll
        for (int i = 0; i < 4; i++) {
            int idx = tid + i * 256;
            int row = idx >> 3;           // 0..127
            int ch  = idx & 7;            // 16B chunk within row (8 chunks)
            int grow = min(row0 + row, N_NODES - 1);
            uint4 u = __ldg((const uint4*)(Xh + (size_t)grow * D + k0 + ch * 8));
            *(uint4*)&As[row][ch * 4] = u;
        }
        // Stage B: 128 cols x 64 halves from Wt rows.
#pragma unroll
        for (int i = 0; i < 4; i++) {
            int idx = tid + i * 256;
            int col = idx >> 3;
            int ch  = idx & 7;
            uint4 u = __ldg((const uint4*)(Bt + (size_t)col * D + k0 + ch * 8));
            *(uint4*)&Bs[col][ch * 4] = u;
        }
        __syncthreads();

#pragma unroll
        for (int ks = 0; ks < 4; ks++) {      // four k16 steps per BK=64
            int kc = ks * 8;
            uint32_t af[4][4];
            uint32_t bf[4][2];
#pragma unroll
            for (int mi = 0; mi < 4; mi++) {
                int base = warp_m * 64 + mi * 16;
                af[mi][0] = As[base + lg    ][kc + lt    ];
                af[mi][1] = As[base + lg + 8][kc + lt    ];
                af[mi][2] = As[base + lg    ][kc + lt + 4];
                af[mi][3] = As[base + lg + 8][kc + lt + 4];
            }
#pragma unroll
            for (int ni = 0; ni < 4; ni++) {
                int col = warp_n * 32 + ni * 8 + lg;
                bf[ni][0] = Bs[col][kc + lt    ];
                bf[ni][1] = Bs[col][kc + lt + 4];
            }
#pragma unroll
            for (int mi = 0; mi < 4; mi++)
#pragma unroll
                for (int ni = 0; ni < 4; ni++)
                    mma_f16(acc[mi][ni], af[mi], bf[ni]);
        }
        __syncthreads();
    }

    // Epilogue: scale by rsqrt(max(deg_out,1)) computed inline from counts.
    const int* cnt_out = g_cnt_out + (size_t)rel * N_NODES;
#pragma unroll
    for (int mi = 0; mi < 4; mi++) {
        int r = row0 + warp_m * 64 + mi * 16 + lg;
        float s0 = 0.0f, s1 = 0.0f;
        if (r < N_NODES)
            s0 = rsqrtf(fmaxf((float)__ldg(&cnt_out[r]), 1.0f));
        if (r + 8 < N_NODES)
            s1 = rsqrtf(fmaxf((float)__ldg(&cnt_out[r + 8]), 1.0f));
#pragma unroll
        for (int ni = 0; ni < 4; ni++) {
            int c = warp_n * 32 + ni * 8 + 2 * lt;
            if (r < N_NODES) {
                __half2 h = __floats2half2_rn(acc[mi][ni][0] * s0,
                                              acc[mi][ni][1] * s0);
                *(__half2*)(Y + (size_t)r * KTOT + rel * D + c) = h;
            }
            if (r + 8 < N_NODES) {
                __half2 h = __floats2half2_rn(acc[mi][ni][2] * s1,
                                              acc[mi][ni][3] * s1);
                *(__half2*)(Y + (size_t)(r + 8) * KTOT + rel * D + c) = h;
            }
        }
    }
}

// ---------------------------------------------------------------------------
// Gather: one warp per dst node, single merged loop, 8-edge unrolled for
// deep MLP. Packed csr p = 4*src+rel is the Y row index; per-edge coef
// rsqrt(deg_in[rel][t]) selected from 4 preloaded registers via p&3.
__device__ __forceinline__ float sel4(int r, float c0, float c1, float c2,
                                      float c3) {
    return (r == 0) ? c0 : (r == 1) ? c1 : (r == 2) ? c2 : c3;
}

__global__ __launch_bounds__(256)
void gather_kernel(const __half* __restrict__ Y, float* __restrict__ out) {
    int warp = (blockIdx.x * blockDim.x + threadIdx.x) >> 5;
    if (warp >= N_NODES) return;
    int lane = threadIdx.x & 31;
    int t = warp;

    int start = __ldg(&g_rowptr[t]);
    int end   = __ldg(&g_rowptr[t + 1]);
    float cs0 = rsqrtf(fmaxf((float)__ldg(&g_cnt_in[0 * N_NODES + t]), 1.0f));
    float cs1 = rsqrtf(fmaxf((float)__ldg(&g_cnt_in[1 * N_NODES + t]), 1.0f));
    float cs2 = rsqrtf(fmaxf((float)__ldg(&g_cnt_in[2 * N_NODES + t]), 1.0f));
    float cs3 = rsqrtf(fmaxf((float)__ldg(&g_cnt_in[3 * N_NODES + t]), 1.0f));

    float a0 = 0.f, a1 = 0.f, a2 = 0.f, a3 = 0.f;

    int j = start;
    for (; j + 8 <= end; j += 8) {
        int p[8];
        uint2 v[8];
#pragma unroll
        for (int k = 0; k < 8; k++) p[k] = __ldg(&g_csr[j + k]);
#pragma unroll
        for (int k = 0; k < 8; k++)
            v[k] = __ldg((const uint2*)(Y + (size_t)p[k] * D) + lane);
#pragma unroll
        for (int k = 0; k < 8; k++) {
            float c = sel4(p[k] & 3, cs0, cs1, cs2, cs3);
            float2 x0 = __half22float2(*(__half2*)&v[k].x);
            float2 x1 = __half22float2(*(__half2*)&v[k].y);
            a0 = fmaf(c, x0.x, a0); a1 = fmaf(c, x0.y, a1);
            a2 = fmaf(c, x1.x, a2); a3 = fmaf(c, x1.y, a3);
        }
    }
    for (; j + 4 <= end; j += 4) {
        int p[4];
        uint2 v[4];
#pragma unroll
        for (int k = 0; k < 4; k++) p[k] = __ldg(&g_csr[j + k]);
#pragma unroll
        for (int k = 0; k < 4; k++)
            v[k] = __ldg((const uint2*)(Y + (size_t)p[k] * D) + lane);
#pragma unroll
        for (int k = 0; k < 4; k++) {
            float c = sel4(p[k] & 3, cs0, cs1, cs2, cs3);
            float2 x0 = __half22float2(*(__half2*)&v[k].x);
            float2 x1 = __half22float2(*(__half2*)&v[k].y);
            a0 = fmaf(c, x0.x, a0); a1 = fmaf(c, x0.y, a1);
            a2 = fmaf(c, x1.x, a2); a3 = fmaf(c, x1.y, a3);
        }
    }
    for (; j < end; j++) {
        int p0 = __ldg(&g_csr[j]);
        uint2 v0 = __ldg((const uint2*)(Y + (size_t)p0 * D) + lane);
        float c = sel4(p0 & 3, cs0, cs1, cs2, cs3);
        float2 x0 = __half22float2(*(__half2*)&v0.x);
        float2 x1 = __half22float2(*(__half2*)&v0.y);
        a0 = fmaf(c, x0.x, a0); a1 = fmaf(c, x0.y, a1);
        a2 = fmaf(c, x1.x, a2); a3 = fmaf(c, x1.y, a3);
    }

    float4 o = make_float4(a0, a1, a2, a3);
    *(float4*)(out + (size_t)t * D + lane * 4) = o;
}

// ---------------------------------------------------------------------------
extern "C" void kernel_launch(void* const* d_in, const int* in_sizes, int n_in,
                              void* d_out, int out_size) {
    const int*   edges = (const int*)d_in[0];    // [4, 2, 600000] int32
    const float* X     = (const float*)d_in[1];  // [100000, 128] f32
    const float* W     = (const float*)d_in[2];  // [4, 128, 128] f32
    float*       out   = (float*)d_out;          // [100000, 128] f32

    void *yp, *xhp, *wtp, *cop, *cip;
    cudaGetSymbolAddress(&yp,  g_Y);
    cudaGetSymbolAddress(&xhp, g_Xh);
    cudaGetSymbolAddress(&wtp, g_Wt);
    cudaGetSymbolAddress(&cop, g_cnt_out);
    cudaGetSymbolAddress(&cip, g_cnt_in);

    cudaMemsetAsync(cop, 0, sizeof(int) * RN, 0);
    cudaMemsetAsync(cip, 0, sizeof(int) * RN, 0);

    {
        degree_kernel<<<(TOT_EDGES + 255) / 256, 256>>>(edges);
    }
    {
        size_t total8 = (size_t)N_NODES * D / 8;
        convert_x_kernel<<<(int)((total8 + 255) / 256), 256>>>(X);
    }
    {
        int total = N_REL * D * D;
        convert_w_kernel<<<(total + 255) / 256, 256>>>(W);
    }
    scan_phase1_kernel<<<SCAN_NBLK, SCAN_BLK>>>();
    scan_phase2_kernel<<<1, 128>>>();
    scan_phase3_kernel<<<SCAN_NBLK, SCAN_BLK>>>();
    {
        csr_fill_kernel<<<(TOT_EDGES + 255) / 256, 256>>>(edges);
    }
    {
        dim3 grid((N_NODES + GBM - 1) / GBM, N_REL);   // (782, 4)
        gemm_f16_kernel<<<grid, 256>>>((const __half*)xhp, (const __half*)wtp,
                                       (__half*)yp);
    }
    {
        long long threads = (long long)N_NODES * 32;
        int blocks = (int)((threads + 255) / 256);
        gather_kernel<<<blocks, 256>>>((const __half*)yp, out);
    }
}